// round 10
// baseline (speedup 1.0000x reference)
#include <cuda_runtime.h>
#include <cmath>
#include <complex>
#include <cstring>

// Problem constants
#define TT   50
#define PAD  49
#define EXT  148              // PAD + TT + PAD
#define BB   50
#define CC   4096
#define BC   (BB * CC)        // 204800 channels
#define NSEC 2
#define NBAND 2
#define CTILE 8               // channels (c) per block
#define BLKT (BB * CTILE)     // 400 threads: thread (b, c_local)

#define MIR_SMEM_BYTES (PAD * BLKT * (int)sizeof(float))   // 78,400

struct FiltCoef {
    // [band][section]
    float b0[NBAND][NSEC];
    float b2[NBAND][NSEC];
    float a1[NBAND][NSEC];
    float a2[NBAND][NSEC];
    float zi0[NBAND][NSEC];
    float zi1[NBAND][NSEC];
};

extern __shared__ float dsm[];   // [PAD][BLKT] mirror-region y values

__global__ void __launch_bounds__(BLKT, 2)
fused_kernel(const float* __restrict__ x, float* __restrict__ out, FiltCoef cf) {
    __shared__ float s_m2 [TT][CTILE];
    __shared__ float s_inv[TT][CTILE];

    const int tid  = threadIdx.x;          // < 400
    const int b    = tid >> 3;             // 0..49  (batch index == stat provider for t=b)
    const int cl   = tid & (CTILE - 1);    // 0..7
    const int band = blockIdx.x;
    const int c    = blockIdx.y * CTILE + cl;
    const int ch   = b * CC + c;           // channel in [0, BC)
    const float* xc = x + ch;
    float* mir = dsm + tid;                // thread-private column, stride BLKT

    const float b00 = cf.b0[band][0], b20 = cf.b2[band][0];
    const float a10 = cf.a1[band][0], a20 = cf.a2[band][0];
    const float b01 = cf.b0[band][1], b21 = cf.b2[band][1];
    const float a11 = cf.a1[band][1], a21 = cf.a2[band][1];

    // central y (ext indices [PAD, PAD+TT)) lives in registers
    float arr[TT];   // 50 floats

    const float x0 = xc[0];
    const float xl = xc[(size_t)(TT - 1) * BC];
    const float tx0 = 2.0f * x0;
    const float txl = 2.0f * xl;

    // ---- forward pass (2 cascaded biquads, DF2T) over the odd extension ----
    {
        const float e0 = tx0 - xc[(size_t)PAD * BC];   // ext[0] = 2*x0 - x[PAD]
        float z00 = cf.zi0[band][0] * e0, z01 = cf.zi1[band][0] * e0;
        float z10 = cf.zi0[band][1] * e0, z11 = cf.zi1[band][1] * e0;

        // left mirror: t = 0..PAD-1, xt = 2*x0 - x[PAD-t]  (state only, no storage)
        #pragma unroll
        for (int t = 0; t < PAD; t++) {
            const float xt = tx0 - xc[(size_t)(PAD - t) * BC];
            const float y0 = fmaf(b00, xt, z00);
            z00 = fmaf(-a10, y0, z01);
            z01 = fmaf(b20, xt, -a20 * y0);
            const float y1 = fmaf(b01, y0, z10);
            z10 = fmaf(-a11, y1, z11);
            z11 = fmaf(b21, y0, -a21 * y1);
        }
        // central: xt = x[t], store y in registers
        #pragma unroll
        for (int t = 0; t < TT; t++) {
            const float xt = xc[(size_t)t * BC];
            const float y0 = fmaf(b00, xt, z00);
            z00 = fmaf(-a10, y0, z01);
            z01 = fmaf(b20, xt, -a20 * y0);
            const float y1 = fmaf(b01, y0, z10);
            z10 = fmaf(-a11, y1, z11);
            z11 = fmaf(b21, y0, -a21 * y1);
            arr[t] = y1;
        }
        // right mirror: xt = 2*xl - x[TT-1-k], store y in smem (consumed once, in order)
        #pragma unroll
        for (int k = 1; k <= PAD; k++) {
            const float xt = txl - xc[(size_t)(TT - 1 - k) * BC];
            const float y0 = fmaf(b00, xt, z00);
            z00 = fmaf(-a10, y0, z01);
            z01 = fmaf(b20, xt, -a20 * y0);
            const float y1 = fmaf(b01, y0, z10);
            z10 = fmaf(-a11, y1, z11);
            z11 = fmaf(b21, y0, -a21 * y1);
            mir[(k - 1) * BLKT] = y1;     // ext index PAD+TT-1+k
        }
    }

    // ---- backward pass: ext index EXT-1 down to PAD ----
    // (steps below PAD only produce discarded outputs; backward state flows
    //  right-to-left, so those steps cannot affect the central outputs)
    {
        const float e = mir[(PAD - 1) * BLKT];   // y at ext index EXT-1
        float z00 = cf.zi0[band][0] * e, z01 = cf.zi1[band][0] * e;
        float z10 = cf.zi0[band][1] * e, z11 = cf.zi1[band][1] * e;

        // mirror region: state evolution only
        #pragma unroll
        for (int k = PAD; k >= 1; k--) {
            const float xt = mir[(k - 1) * BLKT];
            const float y0 = fmaf(b00, xt, z00);
            z00 = fmaf(-a10, y0, z01);
            z01 = fmaf(b20, xt, -a20 * y0);
            const float y1 = fmaf(b01, y0, z10);
            z10 = fmaf(-a11, y1, z11);
            z11 = fmaf(b21, y0, -a21 * y1);
        }
        // central region: overwrite registers with final filtered values
        #pragma unroll
        for (int t = TT - 1; t >= 0; t--) {
            const float xt = arr[t];
            const float y0 = fmaf(b00, xt, z00);
            z00 = fmaf(-a10, y0, z01);
            z01 = fmaf(b20, xt, -a20 * y0);
            const float y1 = fmaf(b01, y0, z10);
            z10 = fmaf(-a11, y1, z11);
            z11 = fmaf(b21, y0, -a21 * y1);
            arr[t] = y1;
        }
    }

    // ---- first demean over T (per-channel), compute own stats ----
    float s = 0.0f;
    #pragma unroll
    for (int t = 0; t < TT; t++) s += arr[t];
    const float m = s * (1.0f / TT);

    float s2 = 0.0f;
    #pragma unroll
    for (int t = 0; t < TT; t++) {
        const float yd = arr[t] - m;
        arr[t] = yd;
        s2 += yd;
    }
    const float m2 = s2 * (1.0f / TT);

    float v = 0.0f;
    #pragma unroll
    for (int t = 0; t < TT; t++) {
        const float d = arr[t] - m2;
        v = fmaf(d, d, v);
    }

    // publish this channel's stats: it is the provider for time index t = b
    s_m2 [b][cl] = m2;
    s_inv[b][cl] = rsqrtf(v * (1.0f / (TT - 1)));
    __syncthreads();

    // ---- normalize with stats of channel (b'=t, c) and write final output ----
    // (mirrors the reference's (T,B,C)-(B,1,C) broadcasting quirk; T==B)
    float* ob = out + (size_t)band * TT * BC + ch;
    #pragma unroll
    for (int t = 0; t < TT; t++)
        ob[(size_t)t * BC] = (arr[t] - s_m2[t][cl]) * s_inv[t][cl];
}

// ---------------- host-side filter design (mirrors reference numpy code) ----------------
static void design_band(double w1, double w2, double sos[NSEC][6], double zi[NSEC][2]) {
    using cd = std::complex<double>;
    const double PI = 3.14159265358979323846;
    const double fs = 2.0;
    const double W1 = 2.0 * fs * tan(PI * w1 / fs);
    const double W2 = 2.0 * fs * tan(PI * w2 / fs);
    const double bw = W2 - W1;
    const double wo = sqrt(W1 * W2);

    cd p_bp[4];
    for (int k = 1; k <= 2; k++) {
        cd p = -std::exp(cd(0.0, PI * (2 * k - 1) / 4.0));
        cd plp = p * (bw / 2.0);
        cd disc = std::sqrt(plp * plp - cd(wo * wo, 0.0));
        p_bp[k - 1] = plp + disc;
        p_bp[k + 1] = plp - disc;
    }
    const double fs2 = 2.0 * fs;   // 4.0
    cd prod(1.0, 0.0);
    for (int i = 0; i < 4; i++) prod *= (cd(fs2, 0.0) - p_bp[i]);
    const double gain = bw * bw * fs2 * fs2 / prod.real();

    cd pos[2];
    int npos = 0;
    for (int i = 0; i < 4; i++) {
        cd pd = (cd(fs2, 0.0) + p_bp[i]) / (cd(fs2, 0.0) - p_bp[i]);
        if (pd.imag() > 0.0 && npos < 2) pos[npos++] = pd;
    }
    for (int s = 0; s < NSEC; s++) {
        const double g = (s == 0) ? gain : 1.0;
        sos[s][0] = g;  sos[s][1] = 0.0;  sos[s][2] = -g;
        sos[s][3] = 1.0;
        sos[s][4] = -2.0 * pos[s].real();
        sos[s][5] = std::norm(pos[s]);
    }
    // sosfilt_zi
    double scale = 1.0;
    for (int s = 0; s < NSEC; s++) {
        const double b0 = sos[s][0], b1 = sos[s][1], b2 = sos[s][2];
        const double a1 = sos[s][4], a2 = sos[s][5];
        const double B0 = b1 - a1 * b0;
        const double B1 = b2 - a2 * b0;
        const double det = 1.0 + a1 + a2;
        zi[s][0] = scale * (B0 + B1) / det;
        zi[s][1] = scale * ((1.0 + a1) * B1 - a2 * B0) / det;
        scale *= (b0 + b1 + b2) / (1.0 + a1 + a2);
    }
}

extern "C" void kernel_launch(void* const* d_in, const int* in_sizes, int n_in,
                              void* d_out, int out_size) {
    const float* x = (const float*)d_in[0];
    float* out = (float*)d_out;

    const double bands[NBAND][2] = { {0.05, 0.15}, {0.2, 0.4} };
    FiltCoef cf;
    for (int b = 0; b < NBAND; b++) {
        double sos[NSEC][6], zi[NSEC][2];
        design_band(bands[b][0], bands[b][1], sos, zi);
        for (int s = 0; s < NSEC; s++) {
            cf.b0[b][s]  = (float)sos[s][0];
            cf.b2[b][s]  = (float)sos[s][2];
            cf.a1[b][s]  = (float)sos[s][4];
            cf.a2[b][s]  = (float)sos[s][5];
            cf.zi0[b][s] = (float)zi[s][0];
            cf.zi1[b][s] = (float)zi[s][1];
        }
    }

    // opt-in for 78.4KB dynamic smem (idempotent, non-stream, capture-safe)
    cudaFuncSetAttribute(fused_kernel,
                         cudaFuncAttributeMaxDynamicSharedMemorySize,
                         MIR_SMEM_BYTES);

    // band on x so the two bands of the same c-tile are launch-adjacent
    // (x input read hits L2 for the second band)
    dim3 grid(NBAND, CC / CTILE);          // 2 x 512
    fused_kernel<<<grid, BLKT, MIR_SMEM_BYTES>>>(x, out, cf);
}

// round 11
// speedup vs baseline: 1.3938x; 1.3938x over previous
#include <cuda_runtime.h>
#include <cmath>

// Problem constants
#define TT   50
#define PAD  49
#define EXT  148              // PAD + TT + PAD
#define BB   50
#define CC   4096
#define BC   (BB * CC)        // 204800 channels
#define NBAND 2
#define BLK  128              // threads per block; one channel per thread, zero smem

// ================= compile-time Butterworth bandpass design =================
// Mirrors the reference numpy code exactly, evaluated in double at compile time
// so coefficients become instruction immediates (FFMA-imm, rt=1).

__host__ __device__ constexpr double c_sin(double x) {
    double t = x, s = x;
    for (int k = 1; k <= 15; k++) { t *= -x * x / ((2.0 * k) * (2.0 * k + 1.0)); s += t; }
    return s;
}
__host__ __device__ constexpr double c_cos(double x) {
    double t = 1.0, s = 1.0;
    for (int k = 1; k <= 15; k++) { t *= -x * x / ((2.0 * k - 1.0) * (2.0 * k)); s += t; }
    return s;
}
__host__ __device__ constexpr double c_tan(double x) { return c_sin(x) / c_cos(x); }
__host__ __device__ constexpr double c_sqrt(double x) {
    if (x <= 0.0) return 0.0;
    double y = x > 1.0 ? x : 1.0;
    for (int i = 0; i < 200; i++) y = 0.5 * (y + x / y);
    return y;
}

struct CD { double re, im; };
__host__ __device__ constexpr CD cmul(CD a, CD b) { return {a.re * b.re - a.im * b.im, a.re * b.im + a.im * b.re}; }
__host__ __device__ constexpr CD cdiv(CD a, CD b) {
    double d = b.re * b.re + b.im * b.im;
    return {(a.re * b.re + a.im * b.im) / d, (a.im * b.re - a.re * b.im) / d};
}
__host__ __device__ constexpr CD csqrt(CD z) {
    double r = c_sqrt(z.re * z.re + z.im * z.im);
    double re = c_sqrt((r + z.re) * 0.5);
    double im = c_sqrt((r - z.re) * 0.5);
    return {re, z.im >= 0.0 ? im : -im};
}

struct BandCoef {
    double b0_0, b2_0, a1_0, a2_0, zi0_0, zi1_0;   // section 0
    double b0_1, b2_1, a1_1, a2_1, zi0_1, zi1_1;   // section 1
};

__host__ __device__ constexpr BandCoef design(double w1, double w2) {
    const double PI = 3.14159265358979323846264338327950288;
    const double RT2_2 = 0.70710678118654752440;   // sqrt(2)/2
    // warped = 2*fs*tan(pi*w/fs), fs=2
    const double W1 = 4.0 * c_tan(PI * w1 / 2.0);
    const double W2 = 4.0 * c_tan(PI * w2 / 2.0);
    const double bw = W2 - W1;
    const double wo = c_sqrt(W1 * W2);

    // analog prototype poles p_k = -exp(i*pi*(2k-1)/4), k=1,2
    CD p[2] = { {-RT2_2, -RT2_2}, {RT2_2, -RT2_2} };
    CD pbp[4] = { {0,0},{0,0},{0,0},{0,0} };
    for (int k = 0; k < 2; k++) {
        CD plp = {p[k].re * bw * 0.5, p[k].im * bw * 0.5};
        CD disc = csqrt({plp.re * plp.re - plp.im * plp.im - wo * wo,
                         2.0 * plp.re * plp.im});
        pbp[k]     = {plp.re + disc.re, plp.im + disc.im};   // concatenate order:
        pbp[k + 2] = {plp.re - disc.re, plp.im - disc.im};   // [p+d , p-d]
    }
    const double fs2 = 4.0;
    CD prod = {1.0, 0.0};
    for (int i = 0; i < 4; i++) prod = cmul(prod, {fs2 - pbp[i].re, -pbp[i].im});
    const double gain = bw * bw * fs2 * fs2 / prod.re;

    CD pos[2] = { {0,0},{0,0} };
    int np = 0;
    for (int i = 0; i < 4; i++) {
        CD pd = cdiv({fs2 + pbp[i].re, pbp[i].im}, {fs2 - pbp[i].re, -pbp[i].im});
        if (pd.im > 0.0 && np < 2) { pos[np] = pd; np++; }
    }

    BandCoef bc = {};
    bc.b0_0 = gain;  bc.b2_0 = -gain;
    bc.a1_0 = -2.0 * pos[0].re;  bc.a2_0 = pos[0].re * pos[0].re + pos[0].im * pos[0].im;
    bc.b0_1 = 1.0;   bc.b2_1 = -1.0;
    bc.a1_1 = -2.0 * pos[1].re;  bc.a2_1 = pos[1].re * pos[1].re + pos[1].im * pos[1].im;

    // sosfilt_zi
    double scale = 1.0;
    {
        const double b0 = bc.b0_0, b2 = bc.b2_0, a1 = bc.a1_0, a2 = bc.a2_0;
        const double B0 = -a1 * b0;              // b1 = 0
        const double B1 = b2 - a2 * b0;
        const double det = 1.0 + a1 + a2;
        bc.zi0_0 = scale * (B0 + B1) / det;
        bc.zi1_0 = scale * ((1.0 + a1) * B1 - a2 * B0) / det;
        scale *= (b0 + b2) / (1.0 + a1 + a2);
    }
    {
        const double b0 = bc.b0_1, b2 = bc.b2_1, a1 = bc.a1_1, a2 = bc.a2_1;
        const double B0 = -a1 * b0;
        const double B1 = b2 - a2 * b0;
        const double det = 1.0 + a1 + a2;
        bc.zi0_1 = scale * (B0 + B1) / det;
        bc.zi1_1 = scale * ((1.0 + a1) * B1 - a2 * B0) / det;
    }
    return bc;
}

// per-band, per-channel normalization stats (channel index = b*C + c)
__device__ float g_m2 [NBAND][BC];
__device__ float g_inv[NBAND][BC];

template <int BAND>
__global__ void __launch_bounds__(BLK)
filtfilt_kernel(const float* __restrict__ x, float* __restrict__ out) {
    constexpr BandCoef bc = (BAND == 0) ? design(0.05, 0.15) : design(0.2, 0.4);
    // compile-time float coefficients -> FFMA immediate forms (rt_SMSP = 1)
    constexpr float b00 = (float)bc.b0_0,  b20 = (float)bc.b2_0;
    constexpr float na10 = (float)(-bc.a1_0), na20 = (float)(-bc.a2_0);
    constexpr float b01 = (float)bc.b0_1,  b21 = (float)bc.b2_1;
    constexpr float na11 = (float)(-bc.a1_1), na21 = (float)(-bc.a2_1);
    constexpr float zi00 = (float)bc.zi0_0, zi10 = (float)bc.zi1_0;
    constexpr float zi01 = (float)bc.zi0_1, zi11 = (float)bc.zi1_1;

    const int ch = blockIdx.x * BLK + threadIdx.x;  // channel in [0, BC)
    const float* xc = x + ch;

    // y for ext indices [PAD, EXT) lives in registers (fully unrolled indexing)
    float arr[EXT - PAD];   // 99 floats

    const float x0 = xc[0];
    const float xl = xc[(size_t)(TT - 1) * BC];
    const float tx0 = 2.0f * x0;
    const float txl = 2.0f * xl;

    // ---- forward pass (2 cascaded biquads, DF2T) over the odd extension ----
    {
        const float e0 = tx0 - xc[(size_t)PAD * BC];   // ext[0] = 2*x0 - x[PAD]
        float z00 = zi00 * e0, z01 = zi10 * e0;
        float z10 = zi01 * e0, z11 = zi11 * e0;

        // left mirror: xt = 2*x0 - x[PAD-t]  (state only, no storage)
        #pragma unroll
        for (int t = 0; t < PAD; t++) {
            const float xt = tx0 - xc[(size_t)(PAD - t) * BC];
            const float y0 = fmaf(b00, xt, z00);
            z00 = fmaf(na10, y0, z01);
            z01 = fmaf(b20, xt, na20 * y0);
            const float y1 = fmaf(b01, y0, z10);
            z10 = fmaf(na11, y1, z11);
            z11 = fmaf(b21, y0, na21 * y1);
        }
        // central: xt = x[t], store y
        #pragma unroll
        for (int t = 0; t < TT; t++) {
            const float xt = xc[(size_t)t * BC];
            const float y0 = fmaf(b00, xt, z00);
            z00 = fmaf(na10, y0, z01);
            z01 = fmaf(b20, xt, na20 * y0);
            const float y1 = fmaf(b01, y0, z10);
            z10 = fmaf(na11, y1, z11);
            z11 = fmaf(b21, y0, na21 * y1);
            arr[t] = y1;
        }
        // right mirror: xt = 2*xl - x[TT-1-k], store y
        #pragma unroll
        for (int k = 1; k <= PAD; k++) {
            const float xt = txl - xc[(size_t)(TT - 1 - k) * BC];
            const float y0 = fmaf(b00, xt, z00);
            z00 = fmaf(na10, y0, z01);
            z01 = fmaf(b20, xt, na20 * y0);
            const float y1 = fmaf(b01, y0, z10);
            z10 = fmaf(na11, y1, z11);
            z11 = fmaf(b21, y0, na21 * y1);
            arr[TT - 1 + k] = y1;
        }
    }

    // ---- backward pass: ext index EXT-1 down to PAD ----
    // (steps below PAD only produce discarded outputs; backward state flows
    //  right-to-left, so those steps cannot affect the central outputs)
    {
        const float e = arr[EXT - PAD - 1];   // y at ext index EXT-1
        float z00 = zi00 * e, z01 = zi10 * e;
        float z10 = zi01 * e, z11 = zi11 * e;
        #pragma unroll
        for (int i = 0; i < EXT - PAD; i++) {   // slot 98 down to 0
            const int s = EXT - PAD - 1 - i;
            const float xt = arr[s];
            const float y0 = fmaf(b00, xt, z00);
            z00 = fmaf(na10, y0, z01);
            z01 = fmaf(b20, xt, na20 * y0);
            const float y1 = fmaf(b01, y0, z10);
            z10 = fmaf(na11, y1, z11);
            z11 = fmaf(b21, y0, na21 * y1);
            if (s < TT) arr[s] = y1;   // central outputs, correct time order
        }
    }

    // ---- first demean over T (per-channel), write yd, gather stats ----
    float s = 0.0f;
    #pragma unroll
    for (int t = 0; t < TT; t++) s += arr[t];
    const float m = s * (1.0f / TT);

    float s2 = 0.0f;
    float* ob = out + (size_t)BAND * TT * BC + ch;
    #pragma unroll
    for (int t = 0; t < TT; t++) {
        const float yd = arr[t] - m;
        arr[t] = yd;
        ob[(size_t)t * BC] = yd;
        s2 += yd;
    }
    const float m2 = s2 * (1.0f / TT);

    float v = 0.0f;
    #pragma unroll
    for (int t = 0; t < TT; t++) {
        const float d = arr[t] - m2;
        v = fmaf(d, d, v);
    }
    g_m2 [BAND][ch] = m2;
    g_inv[BAND][ch] = rsqrtf(v * (1.0f / (TT - 1)));
}

// out[band, t, b, c] = (yd - m2[band, t*C+c]) * inv_s[band, t*C+c]
// (stats indexed by TIME index t, mirroring the reference's broadcasting quirk; T==B)
// Each thread handles the same (t,b,c) position in BOTH bands (shared index math, 2x MLP).
__global__ void __launch_bounds__(256)
normalize_kernel(float4* __restrict__ out4) {
    const int idx4 = blockIdx.x * 256 + threadIdx.x;   // < TT*BC/4 (one band's worth)
    const int c4   = idx4 & (CC / 4 - 1);
    const int t    = idx4 / (BC / 4);                  // time index (band 0 layout)
    const int s4   = t * (CC / 4) + c4;                // stat index (channel b'=t, c)
    const int HALF = TT * BC / 4;                      // elements per band / 4

    float4 v0 = out4[idx4];
    float4 v1 = out4[idx4 + HALF];
    const float4 m0 = ((const float4*)g_m2[0])[s4];
    const float4 s0 = ((const float4*)g_inv[0])[s4];
    const float4 m1 = ((const float4*)g_m2[1])[s4];
    const float4 s1 = ((const float4*)g_inv[1])[s4];
    v0.x = (v0.x - m0.x) * s0.x;  v1.x = (v1.x - m1.x) * s1.x;
    v0.y = (v0.y - m0.y) * s0.y;  v1.y = (v1.y - m1.y) * s1.y;
    v0.z = (v0.z - m0.z) * s0.z;  v1.z = (v1.z - m1.z) * s1.z;
    v0.w = (v0.w - m0.w) * s0.w;  v1.w = (v1.w - m1.w) * s1.w;
    out4[idx4]        = v0;
    out4[idx4 + HALF] = v1;
}

extern "C" void kernel_launch(void* const* d_in, const int* in_sizes, int n_in,
                              void* d_out, int out_size) {
    const float* x = (const float*)d_in[0];
    float* out = (float*)d_out;

    filtfilt_kernel<0><<<BC / BLK, BLK>>>(x, out);   // 1600 blocks
    filtfilt_kernel<1><<<BC / BLK, BLK>>>(x, out);   // x re-read hits L2

    const int q4 = TT * BC / 4;                      // one band's float4 count
    normalize_kernel<<<q4 / 256, 256>>>((float4*)d_out);
}